// round 11
// baseline (speedup 1.0000x reference)
#include <cuda_runtime.h>
#include <cuda_bf16.h>
#include <math.h>
#include <stdint.h>

#define NNODE 8192
#define GTM 128
#define GTN 64
#define GTK 64
#define STAGES 3
#define STAGE_BYTES 24576           // A 16KB + B 8KB
#define GEMM_SMEM (STAGES * STAGE_BYTES)
#define KSPLIT1 2

// ---------------- static device scratch (no allocation) ----------------
__device__ float d_r[NNODE];
__device__ float d_partial[NNODE * 128];                  // rowsum partials [k][mtile]
__device__ __nv_bfloat16 d_adjT[(size_t)NNODE * NNODE];   // A K-major: adjT[m][k] = bf16(adj[k][m])
__device__ __nv_bfloat16 d_XT[256 * NNODE];               // B1 K-major
__device__ __nv_bfloat16 d_G1T[512 * NNODE];              // B2 K-major
__device__ float d_Z[(size_t)2 * NNODE * 512];            // split-K partials / GEMM2 output
__device__ float d_G1[NNODE * 512];

// ---------------- PTX helpers ----------------
__device__ __forceinline__ uint32_t cvta_s(const void* p) {
    return (uint32_t)__cvta_generic_to_shared(p);
}
__device__ __forceinline__ void cp16(uint32_t s, const void* g) {
    asm volatile("cp.async.cg.shared.global [%0], [%1], 16;\n" :: "r"(s), "l"(g));
}
__device__ __forceinline__ void cpCommit() { asm volatile("cp.async.commit_group;\n"); }
__device__ __forceinline__ void cpWait1() { asm volatile("cp.async.wait_group 1;\n" ::: "memory"); }
__device__ __forceinline__ void cpWait0() { asm volatile("cp.async.wait_group 0;\n" ::: "memory"); }

__device__ __forceinline__ void ldsm_x4(uint32_t* d, uint32_t addr) {
    asm volatile("ldmatrix.sync.aligned.m8n8.x4.shared.b16 {%0,%1,%2,%3}, [%4];"
        : "=r"(d[0]), "=r"(d[1]), "=r"(d[2]), "=r"(d[3]) : "r"(addr));
}

__device__ __forceinline__ void mma_bf16(float* c, const uint32_t* a, uint32_t b0, uint32_t b1) {
    asm volatile("mma.sync.aligned.m16n8k16.row.col.f32.bf16.bf16.f32 "
        "{%0,%1,%2,%3}, {%4,%5,%6,%7}, {%8,%9}, {%0,%1,%2,%3};"
        : "+f"(c[0]), "+f"(c[1]), "+f"(c[2]), "+f"(c[3])
        : "r"(a[0]), "r"(a[1]), "r"(a[2]), "r"(a[3]), "r"(b0), "r"(b1));
}

#define SWZ(off) ((off) ^ (((off) >> 3) & 0x70))

// ---------------- block reduction helpers ----------------
template <int NW>
__device__ __forceinline__ float4 blockReduceSum4(float4 v, float4* sb) {
    __syncthreads();
#pragma unroll
    for (int o = 16; o > 0; o >>= 1) {
        v.x += __shfl_down_sync(0xffffffffu, v.x, o);
        v.y += __shfl_down_sync(0xffffffffu, v.y, o);
        v.z += __shfl_down_sync(0xffffffffu, v.z, o);
        v.w += __shfl_down_sync(0xffffffffu, v.w, o);
    }
    int lane = threadIdx.x & 31, w = threadIdx.x >> 5;
    if (lane == 0) sb[w] = v;
    __syncthreads();
    float4 res = sb[0];
#pragma unroll
    for (int i = 1; i < NW; i++) {
        float4 t = sb[i];
        res.x += t.x; res.y += t.y; res.z += t.z; res.w += t.w;
    }
    return res;
}

template <int NW>
__device__ __forceinline__ float blockReduceSum1(float v, float* sb) {
    __syncthreads();
#pragma unroll
    for (int o = 16; o > 0; o >>= 1) v += __shfl_down_sync(0xffffffffu, v, o);
    int lane = threadIdx.x & 31, w = threadIdx.x >> 5;
    if (lane == 0) sb[w] = v;
    __syncthreads();
    float res = sb[0];
#pragma unroll
    for (int i = 1; i < NW; i++) res += sb[i];
    return res;
}

template <int NW>
__device__ __forceinline__ float blockReduceMax1(float v, float* sb) {
    __syncthreads();
#pragma unroll
    for (int o = 16; o > 0; o >>= 1) v = fmaxf(v, __shfl_down_sync(0xffffffffu, v, o));
    int lane = threadIdx.x & 31, w = threadIdx.x >> 5;
    if (lane == 0) sb[w] = v;
    __syncthreads();
    float res = sb[0];
#pragma unroll
    for (int i = 1; i < NW; i++) res = fmaxf(res, sb[i]);
    return res;
}

// ---------------- adjT: transpose+convert adj, plus deterministic rowsum partials ----------------
__global__ void __launch_bounds__(256) adjT_kernel(const float* __restrict__ adj) {
    __shared__ float sm[64][68];
    const int m0 = blockIdx.x * 64, k0 = blockIdx.y * 64;
    const int t = threadIdx.x;
#pragma unroll
    for (int p = 0; p < 4; p++) {
        int idx = t + p * 256;
        int k = idx >> 4, f4 = idx & 15;
        float4 v = *(const float4*)(adj + (size_t)(k0 + k) * NNODE + m0 + f4 * 4);
        *(float4*)&sm[k][f4 * 4] = v;
    }
    __syncthreads();
    if (t < 64) {
        float s = 0.f;
#pragma unroll 16
        for (int j = 0; j < 64; j++) s += sm[t][j];
        d_partial[(size_t)(k0 + t) * 128 + blockIdx.x] = s;
    }
    const int m = t & 63, kq = t >> 6;
    __nv_bfloat16 tmp[16];
#pragma unroll
    for (int j = 0; j < 16; j++) tmp[j] = __float2bfloat16(sm[kq * 16 + j][m]);
    uint4* dst = (uint4*)(d_adjT + (size_t)(m0 + m) * NNODE + k0 + kq * 16);
    dst[0] = ((uint4*)tmp)[0];
    dst[1] = ((uint4*)tmp)[1];
}

// ---------------- finalize r ----------------
__global__ void __launch_bounds__(256) finalize_r_kernel() {
    int k = blockIdx.x * 256 + threadIdx.x;
    const float4* p = (const float4*)(d_partial + (size_t)k * 128);
    float s = 0.f;
#pragma unroll
    for (int j = 0; j < 32; j++) {
        float4 f = p[j];
        s += f.x + f.y + f.z + f.w;
    }
    d_r[k] = (s > 0.f) ? rsqrtf(s) : 0.f;
}

// ---------------- prep XT: XT[b*64+d][k] = bf16(r[k]*x[b][k][d]) ----------------
__global__ void __launch_bounds__(256) prep_xT_kernel(const float* __restrict__ x) {
    __shared__ float sm[64][132];
    const int n0 = blockIdx.x * 128, b = blockIdx.y;
    const int t = threadIdx.x;
#pragma unroll
    for (int p = 0; p < 8; p++) {
        int idx = t + p * 256;
        int ni = idx >> 4, f4 = idx & 15;
        float rv = d_r[n0 + ni];
        float4 v = *(const float4*)(x + ((size_t)b * NNODE + n0 + ni) * 64 + f4 * 4);
        sm[f4 * 4 + 0][ni] = v.x * rv;
        sm[f4 * 4 + 1][ni] = v.y * rv;
        sm[f4 * 4 + 2][ni] = v.z * rv;
        sm[f4 * 4 + 3][ni] = v.w * rv;
    }
    __syncthreads();
    const int d = t >> 2, nq = t & 3;
    __nv_bfloat16 tmp[32];
#pragma unroll
    for (int j = 0; j < 32; j++) tmp[j] = __float2bfloat16(sm[d][nq * 32 + j]);
    uint4* dst = (uint4*)(d_XT + (size_t)(b * 64 + d) * NNODE + n0 + nq * 32);
#pragma unroll
    for (int j = 0; j < 4; j++) dst[j] = ((uint4*)tmp)[j];
}

// ---------------- prep G1T: G1T[c][k] = bf16(r[k]*G1[k][c]) ----------------
__global__ void __launch_bounds__(256) prep_g1T_kernel() {
    __shared__ float sm[64][68];
    const int i0 = blockIdx.x * 64, c0 = blockIdx.y * 64;
    const int t = threadIdx.x;
#pragma unroll
    for (int p = 0; p < 4; p++) {
        int idx = t + p * 256;
        int i = idx >> 4, f4 = idx & 15;
        float rv = d_r[i0 + i];
        float4 v = *(const float4*)(d_G1 + (size_t)(i0 + i) * 512 + c0 + f4 * 4);
        sm[i][f4 * 4 + 0] = v.x * rv;
        sm[i][f4 * 4 + 1] = v.y * rv;
        sm[i][f4 * 4 + 2] = v.z * rv;
        sm[i][f4 * 4 + 3] = v.w * rv;
    }
    __syncthreads();
    const int c = t & 63, iq = t >> 6;
    __nv_bfloat16 tmp[16];
#pragma unroll
    for (int j = 0; j < 16; j++) tmp[j] = __float2bfloat16(sm[iq * 16 + j][c]);
    uint4* dst = (uint4*)(d_G1T + (size_t)(c0 + c) * NNODE + i0 + iq * 16);
    dst[0] = ((uint4*)tmp)[0];
    dst[1] = ((uint4*)tmp)[1];
}

// ---------------- mma.sync GEMM, CTA 128x64, warp 32x32, 3 CTAs/SM ----------------
__global__ void __launch_bounds__(256, 3) gemm_mma_kernel(const __nv_bfloat16* __restrict__ Bmat,
                                                          int Ncols, int ktiles_per_split,
                                                          float* __restrict__ Zout) {
    extern __shared__ char smem[];
    const uint32_t sbase = cvta_s(smem);
    const int t = threadIdx.x;
    const int wid = t >> 5, lane = t & 31;
    const int wm = wid & 3, wn = wid >> 2;     // 4 warps M x 2 warps N
    const int m0 = blockIdx.y * GTM, n0 = blockIdx.x * GTN;
    const int ksp = blockIdx.z;

    auto issue_tile = [&](int st, int kt) {
        uint32_t bufA = sbase + st * STAGE_BYTES;
        uint32_t bufB = bufA + 16384;
        int k0 = kt * GTK;
#pragma unroll
        for (int i = 0; i < 4; i++) {
            int idx = t + i * 256;
            int r = idx >> 3, c = idx & 7;
            cp16(bufA + SWZ(r * 128 + c * 16), d_adjT + (size_t)(m0 + r) * NNODE + k0 + c * 8);
        }
#pragma unroll
        for (int i = 0; i < 2; i++) {
            int idx = t + i * 256;
            int r = idx >> 3, c = idx & 7;
            cp16(bufB + SWZ(r * 128 + c * 16), Bmat + (size_t)(n0 + r) * NNODE + k0 + c * 8);
        }
        cpCommit();
    };

    float acc[2][4][4];
#pragma unroll
    for (int mi = 0; mi < 2; mi++)
#pragma unroll
        for (int j = 0; j < 4; j++)
#pragma unroll
            for (int q = 0; q < 4; q++) acc[mi][j][q] = 0.f;

    const int kt0 = ksp * ktiles_per_split;
    const int kt1 = kt0 + ktiles_per_split;

    issue_tile(0, kt0);
    issue_tile(1, kt0 + 1);

    for (int kt = kt0; kt < kt1; kt++) {
        if (kt + 1 < kt1) cpWait1(); else cpWait0();
        __syncthreads();
        if (kt + 2 < kt1) issue_tile((kt + 2 - kt0) % STAGES, kt + 2);

        uint32_t bufA = sbase + ((kt - kt0) % STAGES) * STAGE_BYTES;
        uint32_t bufB = bufA + 16384;
#pragma unroll
        for (int ks = 0; ks < 4; ks++) {
            uint32_t a[2][4], b[2][4];
            const int colb = ks * 32 + (lane >> 4) * 16;
#pragma unroll
            for (int mi = 0; mi < 2; mi++) {
                int row = wm * 32 + mi * 16 + (lane & 15);
                ldsm_x4(a[mi], bufA + SWZ(row * 128 + colb));
            }
#pragma unroll
            for (int ni = 0; ni < 2; ni++) {
                int row = wn * 32 + ni * 16 + (lane & 15);
                ldsm_x4(b[ni], bufB + SWZ(row * 128 + colb));
            }
#pragma unroll
            for (int mi = 0; mi < 2; mi++) {
#pragma unroll
                for (int j = 0; j < 4; j++) {
                    uint32_t b0 = b[j >> 1][j & 1];
                    uint32_t b1 = b[j >> 1][(j & 1) + 2];
                    mma_bf16(acc[mi][j], a[mi], b0, b1);
                }
            }
        }
    }

    // epilogue: direct stores to split partial buffer
    float* Zp = Zout + (size_t)ksp * NNODE * Ncols;
    const int r0 = lane >> 2, c0 = (lane & 3) * 2;
#pragma unroll
    for (int mi = 0; mi < 2; mi++) {
        int mrow = m0 + wm * 32 + mi * 16 + r0;
#pragma unroll
        for (int j = 0; j < 4; j++) {
            int nc = n0 + wn * 32 + j * 8 + c0;
            *(float2*)(Zp + (size_t)mrow * Ncols + nc) = make_float2(acc[mi][j][0], acc[mi][j][1]);
            *(float2*)(Zp + (size_t)(mrow + 8) * Ncols + nc) = make_float2(acc[mi][j][2], acc[mi][j][3]);
        }
    }
}

// ---------------- epilogue 1: sum splits, self-add, W1+b1, L2 norm, relu, BN -> d_G1 ----------------
__global__ void __launch_bounds__(128) epi1_kernel(const float* __restrict__ x,
                                                   const float* __restrict__ W1,
                                                   const float* __restrict__ b1) {
    __shared__ float ys[4][64];
    __shared__ float4 sb4[4];
    const int i = blockIdx.x, t = threadIdx.x;
    const float ri = d_r[i];

    for (int idx = t; idx < 256; idx += 128) {
        int b = idx >> 6, d = idx & 63;
        float z = d_Z[(size_t)i * 256 + idx] + d_Z[(size_t)NNODE * 256 + (size_t)i * 256 + idx];
        ys[b][d] = ri * z + x[(size_t)b * ((size_t)NNODE * 64) + (size_t)i * 64 + d];
    }
    __syncthreads();

    float bb = __ldg(&b1[t]);
    float a0 = bb, a1 = bb, a2 = bb, a3 = bb;
#pragma unroll 8
    for (int d = 0; d < 64; ++d) {
        float w = __ldg(&W1[d * 128 + t]);
        a0 = fmaf(ys[0][d], w, a0);
        a1 = fmaf(ys[1][d], w, a1);
        a2 = fmaf(ys[2][d], w, a2);
        a3 = fmaf(ys[3][d], w, a3);
    }
    float4 ss = blockReduceSum4<4>(make_float4(a0 * a0, a1 * a1, a2 * a2, a3 * a3), sb4);
    float v0 = fmaxf(a0 / fmaxf(sqrtf(ss.x), 1e-12f), 0.f);
    float v1 = fmaxf(a1 / fmaxf(sqrtf(ss.y), 1e-12f), 0.f);
    float v2 = fmaxf(a2 / fmaxf(sqrtf(ss.z), 1e-12f), 0.f);
    float v3 = fmaxf(a3 / fmaxf(sqrtf(ss.w), 1e-12f), 0.f);

    float s1 = v0 + v1 + v2 + v3;
    float s2 = v0 * v0 + v1 * v1 + v2 * v2 + v3 * v3;
    float4 r2 = blockReduceSum4<4>(make_float4(s1, s2, 0.f, 0.f), sb4);
    float mean = r2.x / 512.f;
    float var = r2.y / 512.f - mean * mean;
    float inv = rsqrtf(var + 1e-5f);

    size_t base = (size_t)i * 512 + t;
    d_G1[base]       = (v0 - mean) * inv;
    d_G1[base + 128] = (v1 - mean) * inv;
    d_G1[base + 256] = (v2 - mean) * inv;
    d_G1[base + 384] = (v3 - mean) * inv;
}

// ---------------- epilogue 2: self-add, W2+b2, L2, relu, BN, proj ----------------
__global__ void __launch_bounds__(256) epi2_kernel(const float* __restrict__ W2,
                                                   const float* __restrict__ b2,
                                                   const float* __restrict__ Wp,
                                                   const float* __restrict__ bp,
                                                   float* __restrict__ pred) {
    __shared__ float y2[4][128];
    __shared__ float g2[4][256];
    __shared__ float4 sb4[8];
    const int t = threadIdx.x;

    for (int nn = 0; nn < 4; nn++) {
        const int i = blockIdx.x * 4 + nn;
        const float ri = d_r[i];
        for (int idx = t; idx < 512; idx += 256) {
            float z = d_Z[(size_t)i * 512 + idx];
            y2[idx >> 7][idx & 127] = ri * z + d_G1[(size_t)i * 512 + idx];
        }
        __syncthreads();

        float bb = __ldg(&b2[t]);
        float a0 = bb, a1 = bb, a2 = bb, a3 = bb;
#pragma unroll 8
        for (int d = 0; d < 128; ++d) {
            float w = __ldg(&W2[d * 256 + t]);
            a0 = fmaf(y2[0][d], w, a0);
            a1 = fmaf(y2[1][d], w, a1);
            a2 = fmaf(y2[2][d], w, a2);
            a3 = fmaf(y2[3][d], w, a3);
        }
        float4 ss = blockReduceSum4<8>(make_float4(a0 * a0, a1 * a1, a2 * a2, a3 * a3), sb4);
        float v0 = fmaxf(a0 / fmaxf(sqrtf(ss.x), 1e-12f), 0.f);
        float v1 = fmaxf(a1 / fmaxf(sqrtf(ss.y), 1e-12f), 0.f);
        float v2 = fmaxf(a2 / fmaxf(sqrtf(ss.z), 1e-12f), 0.f);
        float v3 = fmaxf(a3 / fmaxf(sqrtf(ss.w), 1e-12f), 0.f);

        float s1 = v0 + v1 + v2 + v3;
        float s2 = v0 * v0 + v1 * v1 + v2 * v2 + v3 * v3;
        float4 r2 = blockReduceSum4<8>(make_float4(s1, s2, 0.f, 0.f), sb4);
        float mean = r2.x / 1024.f;
        float var = r2.y / 1024.f - mean * mean;
        float inv = rsqrtf(var + 1e-5f);

        g2[0][t] = (v0 - mean) * inv;
        g2[1][t] = (v1 - mean) * inv;
        g2[2][t] = (v2 - mean) * inv;
        g2[3][t] = (v3 - mean) * inv;
        __syncthreads();

        if (t < 64) {
            int b = t >> 4, c = t & 15;
            float acc = __ldg(&bp[c]);
#pragma unroll 8
            for (int e = 0; e < 256; ++e)
                acc = fmaf(g2[b][e], __ldg(&Wp[e * 16 + c]), acc);
            pred[(size_t)b * ((size_t)NNODE * 16) + (size_t)i * 16 + c] = acc;
        }
        __syncthreads();
    }
}

// ---------------- softmax over node axis ----------------
__global__ void __launch_bounds__(256) softmax_kernel(float* __restrict__ pred) {
    __shared__ float sb[8];
    const int bc = blockIdx.x;
    const int b = bc >> 4, c = bc & 15;
    const int t = threadIdx.x;
    const size_t base = (size_t)b * ((size_t)NNODE * 16) + c;

    float v[32];
#pragma unroll
    for (int j = 0; j < 32; j++) v[j] = pred[base + (size_t)(t + j * 256) * 16];

    float m = -3.4e38f;
#pragma unroll
    for (int j = 0; j < 32; j++) m = fmaxf(m, v[j]);
    m = blockReduceMax1<8>(m, sb);

    float s = 0.f;
#pragma unroll
    for (int j = 0; j < 32; j++) {
        v[j] = expf(v[j] - m);
        s += v[j];
    }
    s = blockReduceSum1<8>(s, sb);
    float invs = 1.f / s;
#pragma unroll
    for (int j = 0; j < 32; j++) pred[base + (size_t)(t + j * 256) * 16] = v[j] * invs;
}

// ---------------- launch ----------------
extern "C" void kernel_launch(void* const* d_in, const int* in_sizes, int n_in,
                              void* d_out, int out_size) {
    const float* x   = (const float*)d_in[0];
    const float* adj = (const float*)d_in[1];
    const float* W1  = (const float*)d_in[2];
    const float* b1  = (const float*)d_in[3];
    const float* W2  = (const float*)d_in[4];
    const float* b2  = (const float*)d_in[5];
    const float* Wp  = (const float*)d_in[6];
    const float* bp  = (const float*)d_in[7];
    float* out = (float*)d_out;

    cudaFuncSetAttribute(gemm_mma_kernel, cudaFuncAttributeMaxDynamicSharedMemorySize, GEMM_SMEM);

    __nv_bfloat16 *XT, *G1T;
    float* Z;
    cudaGetSymbolAddress((void**)&XT, d_XT);
    cudaGetSymbolAddress((void**)&G1T, d_G1T);
    cudaGetSymbolAddress((void**)&Z, d_Z);

    const int KT_ALL = NNODE / GTK;  // 128

    adjT_kernel<<<dim3(128, 128), 256>>>(adj);
    finalize_r_kernel<<<32, 256>>>();
    prep_xT_kernel<<<dim3(64, 4), 256>>>(x);
    // GEMM1: N=256 -> 4 n-tiles, split-K=2 -> 512 CTAs
    gemm_mma_kernel<<<dim3(256 / GTN, NNODE / GTM, KSPLIT1), 256, GEMM_SMEM>>>(
        XT, 256, KT_ALL / KSPLIT1, Z);
    epi1_kernel<<<NNODE, 128>>>(x, W1, b1);
    prep_g1T_kernel<<<dim3(128, 8), 256>>>();
    // GEMM2: N=512 -> 8 n-tiles, no split-K -> 512 CTAs
    gemm_mma_kernel<<<dim3(512 / GTN, NNODE / GTM, 1), 256, GEMM_SMEM>>>(
        G1T, 512, KT_ALL, Z);
    epi2_kernel<<<NNODE / 4, 256>>>(W2, b2, Wp, bp, out);
    softmax_kernel<<<64, 256>>>(out);
}

// round 14
// speedup vs baseline: 1.1271x; 1.1271x over previous
#include <cuda_runtime.h>
#include <cuda_bf16.h>
#include <math.h>
#include <stdint.h>

#define NNODE 8192
#define GTM 128
#define GTN 128
#define GTK 64
#define STAGES 3
#define STAGE_BYTES 32768           // A 16KB + B 16KB
#define GEMM_SMEM (STAGES * STAGE_BYTES)
#define KSPLIT 2

// ---------------- static device scratch (no allocation) ----------------
__device__ float d_r[NNODE];
__device__ float d_partial[NNODE * 128];                  // rowsum partials [k][mtile]
__device__ __nv_bfloat16 d_adjT[(size_t)NNODE * NNODE];   // A K-major: adjT[m][k] = bf16(adj[k][m])
__device__ __nv_bfloat16 d_XT[256 * NNODE];               // B1 K-major
__device__ __nv_bfloat16 d_G1T[512 * NNODE];              // B2 K-major
__device__ float d_Z[(size_t)KSPLIT * NNODE * 512];       // split-K partials
__device__ float d_G1[NNODE * 512];

// ---------------- PTX helpers ----------------
__device__ __forceinline__ uint32_t cvta_s(const void* p) {
    return (uint32_t)__cvta_generic_to_shared(p);
}
__device__ __forceinline__ void cp16(uint32_t s, const void* g) {
    asm volatile("cp.async.cg.shared.global [%0], [%1], 16;\n" :: "r"(s), "l"(g));
}
__device__ __forceinline__ void cpCommit() { asm volatile("cp.async.commit_group;\n"); }
__device__ __forceinline__ void cpWait1() { asm volatile("cp.async.wait_group 1;\n" ::: "memory"); }
__device__ __forceinline__ void cpWait0() { asm volatile("cp.async.wait_group 0;\n" ::: "memory"); }

__device__ __forceinline__ void ldsm_x4(uint32_t* d, uint32_t addr) {
    asm volatile("ldmatrix.sync.aligned.m8n8.x4.shared.b16 {%0,%1,%2,%3}, [%4];"
        : "=r"(d[0]), "=r"(d[1]), "=r"(d[2]), "=r"(d[3]) : "r"(addr));
}

__device__ __forceinline__ void mma_bf16(float* c, const uint32_t* a, uint32_t b0, uint32_t b1) {
    asm volatile("mma.sync.aligned.m16n8k16.row.col.f32.bf16.bf16.f32 "
        "{%0,%1,%2,%3}, {%4,%5,%6,%7}, {%8,%9}, {%0,%1,%2,%3};"
        : "+f"(c[0]), "+f"(c[1]), "+f"(c[2]), "+f"(c[3])
        : "r"(a[0]), "r"(a[1]), "r"(a[2]), "r"(a[3]), "r"(b0), "r"(b1));
}

#define SWZ(off) ((off) ^ (((off) >> 3) & 0x70))

// ---------------- block reduction helpers ----------------
template <int NW>
__device__ __forceinline__ float4 blockReduceSum4(float4 v, float4* sb) {
    __syncthreads();
#pragma unroll
    for (int o = 16; o > 0; o >>= 1) {
        v.x += __shfl_down_sync(0xffffffffu, v.x, o);
        v.y += __shfl_down_sync(0xffffffffu, v.y, o);
        v.z += __shfl_down_sync(0xffffffffu, v.z, o);
        v.w += __shfl_down_sync(0xffffffffu, v.w, o);
    }
    int lane = threadIdx.x & 31, w = threadIdx.x >> 5;
    if (lane == 0) sb[w] = v;
    __syncthreads();
    float4 res = sb[0];
#pragma unroll
    for (int i = 1; i < NW; i++) {
        float4 t = sb[i];
        res.x += t.x; res.y += t.y; res.z += t.z; res.w += t.w;
    }
    return res;
}

template <int NW>
__device__ __forceinline__ float blockReduceSum1(float v, float* sb) {
    __syncthreads();
#pragma unroll
    for (int o = 16; o > 0; o >>= 1) v += __shfl_down_sync(0xffffffffu, v, o);
    int lane = threadIdx.x & 31, w = threadIdx.x >> 5;
    if (lane == 0) sb[w] = v;
    __syncthreads();
    float res = sb[0];
#pragma unroll
    for (int i = 1; i < NW; i++) res += sb[i];
    return res;
}

template <int NW>
__device__ __forceinline__ float blockReduceMax1(float v, float* sb) {
    __syncthreads();
#pragma unroll
    for (int o = 16; o > 0; o >>= 1) v = fmaxf(v, __shfl_down_sync(0xffffffffu, v, o));
    int lane = threadIdx.x & 31, w = threadIdx.x >> 5;
    if (lane == 0) sb[w] = v;
    __syncthreads();
    float res = sb[0];
#pragma unroll
    for (int i = 1; i < NW; i++) res = fmaxf(res, sb[i]);
    return res;
}

// ---------------- adjT: transpose+convert adj, plus deterministic rowsum partials ----------------
__global__ void __launch_bounds__(256) adjT_kernel(const float* __restrict__ adj) {
    __shared__ float sm[64][68];
    const int m0 = blockIdx.x * 64, k0 = blockIdx.y * 64;
    const int t = threadIdx.x;
#pragma unroll
    for (int p = 0; p < 4; p++) {
        int idx = t + p * 256;
        int k = idx >> 4, f4 = idx & 15;
        float4 v = *(const float4*)(adj + (size_t)(k0 + k) * NNODE + m0 + f4 * 4);
        *(float4*)&sm[k][f4 * 4] = v;
    }
    __syncthreads();
    if (t < 64) {
        float s = 0.f;
#pragma unroll 16
        for (int j = 0; j < 64; j++) s += sm[t][j];
        d_partial[(size_t)(k0 + t) * 128 + blockIdx.x] = s;
    }
    const int m = t & 63, kq = t >> 6;
    __nv_bfloat16 tmp[16];
#pragma unroll
    for (int j = 0; j < 16; j++) tmp[j] = __float2bfloat16(sm[kq * 16 + j][m]);
    uint4* dst = (uint4*)(d_adjT + (size_t)(m0 + m) * NNODE + k0 + kq * 16);
    dst[0] = ((uint4*)tmp)[0];
    dst[1] = ((uint4*)tmp)[1];
}

// ---------------- finalize r ----------------
__global__ void __launch_bounds__(256) finalize_r_kernel() {
    int k = blockIdx.x * 256 + threadIdx.x;
    const float4* p = (const float4*)(d_partial + (size_t)k * 128);
    float s = 0.f;
#pragma unroll
    for (int j = 0; j < 32; j++) {
        float4 f = p[j];
        s += f.x + f.y + f.z + f.w;
    }
    d_r[k] = (s > 0.f) ? rsqrtf(s) : 0.f;
}

// ---------------- prep XT: XT[b*64+d][k] = bf16(r[k]*x[b][k][d]) ----------------
__global__ void __launch_bounds__(256) prep_xT_kernel(const float* __restrict__ x) {
    __shared__ float sm[64][132];
    const int n0 = blockIdx.x * 128, b = blockIdx.y;
    const int t = threadIdx.x;
#pragma unroll
    for (int p = 0; p < 8; p++) {
        int idx = t + p * 256;
        int ni = idx >> 4, f4 = idx & 15;
        float rv = d_r[n0 + ni];
        float4 v = *(const float4*)(x + ((size_t)b * NNODE + n0 + ni) * 64 + f4 * 4);
        sm[f4 * 4 + 0][ni] = v.x * rv;
        sm[f4 * 4 + 1][ni] = v.y * rv;
        sm[f4 * 4 + 2][ni] = v.z * rv;
        sm[f4 * 4 + 3][ni] = v.w * rv;
    }
    __syncthreads();
    const int d = t >> 2, nq = t & 3;
    __nv_bfloat16 tmp[32];
#pragma unroll
    for (int j = 0; j < 32; j++) tmp[j] = __float2bfloat16(sm[d][nq * 32 + j]);
    uint4* dst = (uint4*)(d_XT + (size_t)(b * 64 + d) * NNODE + n0 + nq * 32);
#pragma unroll
    for (int j = 0; j < 4; j++) dst[j] = ((uint4*)tmp)[j];
}

// ---------------- prep G1T: G1T[c][k] = bf16(r[k]*G1[k][c]) ----------------
__global__ void __launch_bounds__(256) prep_g1T_kernel() {
    __shared__ float sm[64][68];
    const int i0 = blockIdx.x * 64, c0 = blockIdx.y * 64;
    const int t = threadIdx.x;
#pragma unroll
    for (int p = 0; p < 4; p++) {
        int idx = t + p * 256;
        int i = idx >> 4, f4 = idx & 15;
        float rv = d_r[i0 + i];
        float4 v = *(const float4*)(d_G1 + (size_t)(i0 + i) * 512 + c0 + f4 * 4);
        sm[i][f4 * 4 + 0] = v.x * rv;
        sm[i][f4 * 4 + 1] = v.y * rv;
        sm[i][f4 * 4 + 2] = v.z * rv;
        sm[i][f4 * 4 + 3] = v.w * rv;
    }
    __syncthreads();
    const int c = t & 63, iq = t >> 6;
    __nv_bfloat16 tmp[16];
#pragma unroll
    for (int j = 0; j < 16; j++) tmp[j] = __float2bfloat16(sm[iq * 16 + j][c]);
    uint4* dst = (uint4*)(d_G1T + (size_t)(c0 + c) * NNODE + i0 + iq * 16);
    dst[0] = ((uint4*)tmp)[0];
    dst[1] = ((uint4*)tmp)[1];
}

// ---------------- mma.sync GEMM (round-9 best config), split-K over blockIdx.z ----------------
__global__ void __launch_bounds__(256, 2) gemm_mma_kernel(const __nv_bfloat16* __restrict__ Bmat,
                                                          int Ncols, float* __restrict__ Zout) {
    extern __shared__ char smem[];
    const uint32_t sbase = cvta_s(smem);
    const int t = threadIdx.x;
    const int wid = t >> 5, lane = t & 31;
    const int wm = wid >> 2, wn = wid & 3;     // 2 warps M x 4 warps N
    const int m0 = blockIdx.y * GTM, n0 = blockIdx.x * GTN;
    const int ksp = blockIdx.z;

    auto issue_tile = [&](int st, int kt) {
        uint32_t bufA = sbase + st * STAGE_BYTES;
        uint32_t bufB = bufA + 16384;
        int k0 = kt * GTK;
#pragma unroll
        for (int i = 0; i < 4; i++) {
            int idx = t + i * 256;
            int r = idx >> 3, c = idx & 7;
            cp16(bufA + SWZ(r * 128 + c * 16), d_adjT + (size_t)(m0 + r) * NNODE + k0 + c * 8);
        }
#pragma unroll
        for (int i = 0; i < 4; i++) {
            int idx = t + i * 256;
            int r = idx >> 3, c = idx & 7;
            cp16(bufB + SWZ(r * 128 + c * 16), Bmat + (size_t)(n0 + r) * NNODE + k0 + c * 8);
        }
        cpCommit();
    };

    float acc[4][4][4];
#pragma unroll
    for (int mi = 0; mi < 4; mi++)
#pragma unroll
        for (int j = 0; j < 4; j++)
#pragma unroll
            for (int q = 0; q < 4; q++) acc[mi][j][q] = 0.f;

    const int KT_ALL = NNODE / GTK;          // 128
    const int KT_PER = KT_ALL / KSPLIT;      // 64
    const int kt0 = ksp * KT_PER;
    const int kt1 = kt0 + KT_PER;

    issue_tile(0, kt0);
    issue_tile(1, kt0 + 1);

    for (int kt = kt0; kt < kt1; kt++) {
        if (kt + 1 < kt1) cpWait1(); else cpWait0();
        __syncthreads();
        if (kt + 2 < kt1) issue_tile((kt + 2 - kt0) % STAGES, kt + 2);

        uint32_t bufA = sbase + ((kt - kt0) % STAGES) * STAGE_BYTES;
        uint32_t bufB = bufA + 16384;
#pragma unroll
        for (int ks = 0; ks < 4; ks++) {
            uint32_t a[4][4], b[2][4];
            const int colb = ks * 32 + (lane >> 4) * 16;
#pragma unroll
            for (int mi = 0; mi < 4; mi++) {
                int row = wm * 64 + mi * 16 + (lane & 15);
                ldsm_x4(a[mi], bufA + SWZ(row * 128 + colb));
            }
#pragma unroll
            for (int ni = 0; ni < 2; ni++) {
                int row = wn * 32 + ni * 16 + (lane & 15);
                ldsm_x4(b[ni], bufB + SWZ(row * 128 + colb));
            }
#pragma unroll
            for (int mi = 0; mi < 4; mi++) {
#pragma unroll
                for (int j = 0; j < 4; j++) {
                    uint32_t b0 = b[j >> 1][j & 1];
                    uint32_t b1 = b[j >> 1][(j & 1) + 2];
                    mma_bf16(acc[mi][j], a[mi], b0, b1);
                }
            }
        }
    }

    float* Zp = Zout + (size_t)ksp * NNODE * Ncols;
    const int r0 = lane >> 2, c0 = (lane & 3) * 2;
#pragma unroll
    for (int mi = 0; mi < 4; mi++) {
        int mrow = m0 + wm * 64 + mi * 16 + r0;
#pragma unroll
        for (int j = 0; j < 4; j++) {
            int nc = n0 + wn * 32 + j * 8 + c0;
            *(float2*)(Zp + (size_t)mrow * Ncols + nc) = make_float2(acc[mi][j][0], acc[mi][j][1]);
            *(float2*)(Zp + (size_t)(mrow + 8) * Ncols + nc) = make_float2(acc[mi][j][2], acc[mi][j][3]);
        }
    }
}

// ---------------- epilogue 1: 4 nodes/block, W1 read once ----------------
__global__ void __launch_bounds__(128) epi1_kernel(const float* __restrict__ x,
                                                   const float* __restrict__ W1,
                                                   const float* __restrict__ b1) {
    __shared__ float ys[16][64];   // [nn*4+b][d]
    __shared__ float4 sb4[4];
    const int i0 = blockIdx.x * 4, t = threadIdx.x;  // 128 threads, t = h

    // load 4 nodes x 256 (Z splits summed, self-add)
#pragma unroll
    for (int p = 0; p < 8; p++) {
        int idx = t + p * 128;       // 0..1023
        int nn = idx >> 8, rem = idx & 255;
        int b = rem >> 6, d = rem & 63;
        int i = i0 + nn;
        float z = d_Z[(size_t)i * 256 + rem] + d_Z[(size_t)NNODE * 256 + (size_t)i * 256 + rem];
        ys[nn * 4 + b][d] = d_r[i] * z + x[((size_t)b * NNODE + i) * 64 + d];
    }
    __syncthreads();

    float bb = __ldg(&b1[t]);
    float acc[16];
#pragma unroll
    for (int q = 0; q < 16; q++) acc[q] = bb;
#pragma unroll 4
    for (int d = 0; d < 64; ++d) {
        float w = __ldg(&W1[d * 128 + t]);
#pragma unroll
        for (int q = 0; q < 16; q++) acc[q] = fmaf(ys[q][d], w, acc[q]);
    }

#pragma unroll
    for (int nn = 0; nn < 4; nn++) {
        float a0 = acc[nn * 4 + 0], a1 = acc[nn * 4 + 1], a2 = acc[nn * 4 + 2], a3 = acc[nn * 4 + 3];
        float4 ss = blockReduceSum4<4>(make_float4(a0 * a0, a1 * a1, a2 * a2, a3 * a3), sb4);
        float v0 = fmaxf(a0 / fmaxf(sqrtf(ss.x), 1e-12f), 0.f);
        float v1 = fmaxf(a1 / fmaxf(sqrtf(ss.y), 1e-12f), 0.f);
        float v2 = fmaxf(a2 / fmaxf(sqrtf(ss.z), 1e-12f), 0.f);
        float v3 = fmaxf(a3 / fmaxf(sqrtf(ss.w), 1e-12f), 0.f);

        float s1 = v0 + v1 + v2 + v3;
        float s2 = v0 * v0 + v1 * v1 + v2 * v2 + v3 * v3;
        float4 r2 = blockReduceSum4<4>(make_float4(s1, s2, 0.f, 0.f), sb4);
        float mean = r2.x / 512.f;
        float var = r2.y / 512.f - mean * mean;
        float inv = rsqrtf(var + 1e-5f);

        size_t base = (size_t)(i0 + nn) * 512 + t;
        d_G1[base]       = (v0 - mean) * inv;
        d_G1[base + 128] = (v1 - mean) * inv;
        d_G1[base + 256] = (v2 - mean) * inv;
        d_G1[base + 384] = (v3 - mean) * inv;
    }
}

// ---------------- epilogue 2: 4 nodes/block, W2 read once, fused proj ----------------
__global__ void __launch_bounds__(256) epi2_kernel(const float* __restrict__ W2,
                                                   const float* __restrict__ b2,
                                                   const float* __restrict__ Wp,
                                                   const float* __restrict__ bp,
                                                   float* __restrict__ pred) {
    __shared__ float y2[16][128];   // 8KB
    __shared__ float g2[16][256];   // 16KB
    __shared__ float4 sb4[8];
    const int i0 = blockIdx.x * 4, t = threadIdx.x;  // 256 threads, t = e

    // load 4 nodes x 512 (Z splits summed, self-add)
#pragma unroll
    for (int p = 0; p < 8; p++) {
        int idx = t + p * 256;       // 0..2047
        int nn = idx >> 9, rem = idx & 511;
        int b = rem >> 7, d = rem & 127;
        int i = i0 + nn;
        float z = d_Z[(size_t)i * 512 + rem] + d_Z[(size_t)NNODE * 512 + (size_t)i * 512 + rem];
        y2[nn * 4 + b][d] = d_r[i] * z + d_G1[(size_t)i * 512 + rem];
    }
    __syncthreads();

    float bb = __ldg(&b2[t]);
    float acc[16];
#pragma unroll
    for (int q = 0; q < 16; q++) acc[q] = bb;
#pragma unroll 4
    for (int d = 0; d < 128; ++d) {
        float w = __ldg(&W2[d * 256 + t]);
#pragma unroll
        for (int q = 0; q < 16; q++) acc[q] = fmaf(y2[q][d], w, acc[q]);
    }

#pragma unroll
    for (int nn = 0; nn < 4; nn++) {
        float a0 = acc[nn * 4 + 0], a1 = acc[nn * 4 + 1], a2 = acc[nn * 4 + 2], a3 = acc[nn * 4 + 3];
        float4 ss = blockReduceSum4<8>(make_float4(a0 * a0, a1 * a1, a2 * a2, a3 * a3), sb4);
        float v0 = fmaxf(a0 / fmaxf(sqrtf(ss.x), 1e-12f), 0.f);
        float v1 = fmaxf(a1 / fmaxf(sqrtf(ss.y), 1e-12f), 0.f);
        float v2 = fmaxf(a2 / fmaxf(sqrtf(ss.z), 1e-12f), 0.f);
        float v3 = fmaxf(a3 / fmaxf(sqrtf(ss.w), 1e-12f), 0.f);

        float s1 = v0 + v1 + v2 + v3;
        float s2 = v0 * v0 + v1 * v1 + v2 * v2 + v3 * v3;
        float4 r2 = blockReduceSum4<8>(make_float4(s1, s2, 0.f, 0.f), sb4);
        float mean = r2.x / 1024.f;
        float var = r2.y / 1024.f - mean * mean;
        float inv = rsqrtf(var + 1e-5f);

        g2[nn * 4 + 0][t] = (v0 - mean) * inv;
        g2[nn * 4 + 1][t] = (v1 - mean) * inv;
        g2[nn * 4 + 2][t] = (v2 - mean) * inv;
        g2[nn * 4 + 3][t] = (v3 - mean) * inv;
    }
    __syncthreads();

    // proj: 4 nodes x 4 batches x 16 classes = 256 outputs, one per thread
    {
        int nn = t >> 6, b = (t >> 4) & 3, c = t & 15;
        const float* grow = g2[nn * 4 + b];
        float acc2 = __ldg(&bp[c]);
#pragma unroll 8
        for (int e = 0; e < 256; ++e)
            acc2 = fmaf(grow[e], __ldg(&Wp[e * 16 + c]), acc2);
        pred[(size_t)b * ((size_t)NNODE * 16) + (size_t)(i0 + nn) * 16 + c] = acc2;
    }
}

// ---------------- softmax over node axis ----------------
__global__ void __launch_bounds__(256) softmax_kernel(float* __restrict__ pred) {
    __shared__ float sb[8];
    const int bc = blockIdx.x;
    const int b = bc >> 4, c = bc & 15;
    const int t = threadIdx.x;
    const size_t base = (size_t)b * ((size_t)NNODE * 16) + c;

    float v[32];
#pragma unroll
    for (int j = 0; j < 32; j++) v[j] = pred[base + (size_t)(t + j * 256) * 16];

    float m = -3.4e38f;
#pragma unroll
    for (int j = 0; j < 32; j++) m = fmaxf(m, v[j]);
    m = blockReduceMax1<8>(m, sb);

    float s = 0.f;
#pragma unroll
    for (int j = 0; j < 32; j++) {
        v[j] = expf(v[j] - m);
        s += v[j];
    }
    s = blockReduceSum1<8>(s, sb);
    float invs = 1.f / s;
#pragma unroll
    for (int j = 0; j < 32; j++) pred[base + (size_t)(t + j * 256) * 16] = v[j] * invs;
}

// ---------------- launch ----------------
extern "C" void kernel_launch(void* const* d_in, const int* in_sizes, int n_in,
                              void* d_out, int out_size) {
    const float* x   = (const float*)d_in[0];
    const float* adj = (const float*)d_in[1];
    const float* W1  = (const float*)d_in[2];
    const float* b1  = (const float*)d_in[3];
    const float* W2  = (const float*)d_in[4];
    const float* b2  = (const float*)d_in[5];
    const float* Wp  = (const float*)d_in[6];
    const float* bp  = (const float*)d_in[7];
    float* out = (float*)d_out;

    cudaFuncSetAttribute(gemm_mma_kernel, cudaFuncAttributeMaxDynamicSharedMemorySize, GEMM_SMEM);

    __nv_bfloat16 *XT, *G1T;
    float* Z;
    cudaGetSymbolAddress((void**)&XT, d_XT);
    cudaGetSymbolAddress((void**)&G1T, d_G1T);
    cudaGetSymbolAddress((void**)&Z, d_Z);

    adjT_kernel<<<dim3(128, 128), 256>>>(adj);
    finalize_r_kernel<<<32, 256>>>();
    prep_xT_kernel<<<dim3(64, 4), 256>>>(x);
    gemm_mma_kernel<<<dim3(256 / GTN, NNODE / GTM, KSPLIT), 256, GEMM_SMEM>>>(XT, 256, Z);
    epi1_kernel<<<NNODE / 4, 128>>>(x, W1, b1);
    prep_g1T_kernel<<<dim3(128, 8), 256>>>();
    gemm_mma_kernel<<<dim3(512 / GTN, NNODE / GTM, KSPLIT), 256, GEMM_SMEM>>>(G1T, 512, Z);
    epi2_kernel<<<NNODE / 4, 256>>>(W2, b2, Wp, bp, out);
    softmax_kernel<<<64, 256>>>(out);
}